// round 17
// baseline (speedup 1.0000x reference)
#include <cuda_runtime.h>
#include <cooperative_groups.h>
#include <math.h>
#include <stdint.h>

namespace cg = cooperative_groups;

// ---------------------------------------------------------------------------
// LogNCDE depth-2 log-ODE scan, 4-CTA cluster per batch element (128 CTAs).
// Rank r owns channels {2r,2r+1} and Wv2 rows [128r,128r+128).
// v16 = v15 engine with warp-local partial reduction: warp w owns rows
// 16w..16w+15; lane = (rg=l>>3, kq=l&7). Same 4-row x k-octant register
// tiles and smem partials, but each warp reduces its own partials after a
// __syncwarp (no CTA barrier between matvec and reduce). 7 CTA barriers +
// 2 cluster.syncs per step. Parallel prep computes sigs + h0.
// ---------------------------------------------------------------------------

namespace {
constexpr int kB   = 32;
constexpr int kT   = 2049;
constexpr int kD   = 8;
constexpr int kS   = 64;
constexpr int kH   = 128;
constexpr int kP   = 28;
constexpr int kNW  = 128;
constexpr int kWin = 16;
constexpr int kOut = 8;
constexpr int CL   = 4;
constexpr int NT   = 256;
constexpr int SIGBLK = (kB * kNW) / 256;   // 16 sig blocks
constexpr int PREPBLK = SIGBLK + kB;       // + 32 h0 blocks = 48

// shared-memory float offsets (16B aligned)
constexpr int OFF_SIGS  = 0;        // [128][36]
constexpr int OFF_CH    = 4608;     // [128][16]
constexpr int OFF_BV0   = 6656;     // 128
constexpr int OFF_BV1   = 6784;     // 128
constexpr int OFF_BV2S  = 6912;     // 128
constexpr int OFF_WR    = 7040;     // 512
constexpr int OFF_BR    = 7552;     // 16
constexpr int OFF_HH    = 7568;     // [129][64]
constexpr int OFF_Z0    = 15824;    // 128
constexpr int OFF_D0    = 15952;    // 128
constexpr int OFF_Z1    = 16080;    // 128
constexpr int OFF_D1    = 16208;    // 128
constexpr int OFF_V     = 16336;    // 512 (single buffer)
constexpr int OFF_TDS   = 16848;    // 128
constexpr int OFF_WT    = 16976;    // 2 x 64
constexpr int OFF_PT    = 17104;    // 2 x 128
constexpr int OFF_UT    = 17360;    // 2 x 128
constexpr int OFF_RD    = 17616;    // 128
constexpr int OFF_RSLOT = 17744;    // 4 x 64
constexpr int OFF_PART  = 18000;    // ch0: 1024, pad 16, ch1: 1024
constexpr int PCH1      = 1040;     // ch1 partial region float offset (bank shift)
constexpr int SMEMF     = 20064;    // ~80 KB
}  // namespace

__device__ float g_sigs[kB * kNW * 36];   // per-batch window signatures
__device__ float g_h0[kB * kS];           // per-batch initial state

static __device__ const int c_II[kP] =
    {0,0,0,0,0,0,0,1,1,1,1,1,1,2,2,2,2,2,3,3,3,3,4,4,4,5,5,6};
static __device__ const int c_JJ[kP] =
    {1,2,3,4,5,6,7,2,3,4,5,6,7,3,4,5,6,7,4,5,6,7,5,6,7,6,7,7};

__device__ __forceinline__ int pidx(int i, int j) {   // Lyndon pair index, i<j
    return 7 * i - (i * (i - 1)) / 2 + (j - i - 1);
}
__device__ __forceinline__ float dot4(float4 w, float4 v, float acc) {
    acc = fmaf(w.x, v.x, acc); acc = fmaf(w.y, v.y, acc);
    acc = fmaf(w.z, v.z, acc); acc = fmaf(w.w, v.w, acc);
    return acc;
}
__device__ __forceinline__ float tanh_ap(float x) {
    float r; asm("tanh.approx.f32 %0, %1;" : "=f"(r) : "f"(x)); return r;
}
__device__ __forceinline__ void sp_sg(float s, float& z, float& d) {
    if (s > 20.f) { z = s; d = 1.f; }
    else {
        float e = __expf(s);
        float inv = __frcp_rn(1.f + e);
        z = __logf(1.f + e);
        d = e * inv;
    }
}
__device__ __forceinline__ float sp_f(float x) {   // accurate (one-time h0)
    return (x > 20.f) ? x : log1pf(expf(x));
}

// ============ prep kernel: sigs (blocks 0..15) + h0 (blocks 16..47) ========
__global__ __launch_bounds__(256, 1)
void logncde_prep_kernel(
    const float* __restrict__ x,
    const float* __restrict__ Wi0, const float* __restrict__ bi0,
    const float* __restrict__ Wi1, const float* __restrict__ bi1,
    const float* __restrict__ Wi2, const float* __restrict__ bi2)
{
    __shared__ float z0s[kH], z1s[kH];
    const int blk = blockIdx.x;
    const int t = threadIdx.x;

    if (blk < SIGBLK) {
        int g = blk * 256 + t;
        int b = g >> 7, win = g & 127;
        const float4* xb =
            (const float4*)(x + (size_t)b * kT * kD + (size_t)win * kWin * kD);
        float cum[kD], prev[kD], Mm[kD * kD];
        {
            float4 p0 = xb[0], p1 = xb[1];
            prev[0] = p0.x; prev[1] = p0.y; prev[2] = p0.z; prev[3] = p0.w;
            prev[4] = p1.x; prev[5] = p1.y; prev[6] = p1.z; prev[7] = p1.w;
        }
        #pragma unroll
        for (int i = 0; i < kD; i++) cum[i] = 0.f;
        #pragma unroll
        for (int i = 0; i < kD * kD; i++) Mm[i] = 0.f;
        #pragma unroll
        for (int w = 0; w < kWin; w++) {
            float4 c0 = xb[2 * (w + 1)], c1 = xb[2 * (w + 1) + 1];
            float cur[kD] = {c0.x, c0.y, c0.z, c0.w, c1.x, c1.y, c1.z, c1.w};
            float dl[kD];
            #pragma unroll
            for (int j = 0; j < kD; j++) {
                dl[j] = cur[j] - prev[j];
                prev[j] = cur[j];
            }
            #pragma unroll
            for (int i = 0; i < kD; i++)
                #pragma unroll
                for (int j = 0; j < kD; j++)
                    Mm[i * kD + j] = fmaf(cum[i], dl[j], Mm[i * kD + j]);
            #pragma unroll
            for (int i = 0; i < kD; i++) cum[i] += dl[i];
        }
        float* sgw = &g_sigs[((size_t)b * kNW + win) * 36];
        #pragma unroll
        for (int i = 0; i < kD; i++) sgw[i] = cum[i];
        #pragma unroll
        for (int p = 0; p < kP; p++) {
            int i = c_II[p], j = c_JJ[p];
            sgw[8 + p] = 0.5f * (Mm[i * kD + j] - Mm[j * kD + i]);
        }
    } else {
        int b = blk - SIGBLK;
        const float* x0 = x + (size_t)b * kT * kD;
        if (t < kH) {
            float acc = bi0[t];
            #pragma unroll
            for (int k = 0; k < kD; k++) acc = fmaf(Wi0[t * kD + k], x0[k], acc);
            z0s[t] = sp_f(acc);
        }
        __syncthreads();
        if (t < kH) {
            float acc = bi1[t];
            #pragma unroll 16
            for (int k = 0; k < kH; k++) acc = fmaf(Wi1[t * kH + k], z0s[k], acc);
            z1s[t] = sp_f(acc);
        }
        __syncthreads();
        if (t < kS) {
            float acc = bi2[t];
            #pragma unroll 16
            for (int k = 0; k < kH; k++) acc = fmaf(Wi2[t * kH + k], z1s[k], acc);
            g_h0[b * kS + t] = acc;
        }
    }
}

// ============================== scan kernel ================================
__global__ __launch_bounds__(NT, 1) __cluster_dims__(CL, 1, 1)
void logncde_v16_kernel(
    const float* __restrict__ Wv0, const float* __restrict__ bv0,
    const float* __restrict__ Wv1, const float* __restrict__ bv1,
    const float* __restrict__ Wv2, const float* __restrict__ bv2,
    const float* __restrict__ Wr,  const float* __restrict__ br,
    float* __restrict__ out)
{
    extern __shared__ float sm[];
    cg::cluster_group cluster = cg::this_cluster();
    const int t    = threadIdx.x;
    const int rank = (int)cluster.block_rank();
    const int b    = blockIdx.x >> 2;
    const int d0g  = 2 * rank;
    const int w    = t >> 5;          // warp id: owns rows 16w..16w+15
    const int l    = t & 31;          // lane
    const int rg   = l >> 3;          // 4-row block within warp (0..3)
    const int kq   = l & 7;           // k-octant
    const int row0 = 16 * w + 4 * rg; // first owned row
    const int lr   = l & 15;          // reduce row index within warp
    const int lch  = l >> 4;          // reduce channel (E/F)

    float* peer[CL - 1];
    #pragma unroll
    for (int p = 1; p < CL; p++)
        peer[p - 1] = cluster.map_shared_rank(sm, (rank + p) & (CL - 1));

    // ---- register weight tiles: 4 rows (row0..row0+3) x k-octant kq ----
    float4 w0r[8], w1r[16], w2r[16];
    {
        const float4* W0 = (const float4*)Wv0;
        #pragma unroll
        for (int r = 0; r < 4; r++)
            #pragma unroll
            for (int j = 0; j < 2; j++)
                w0r[r * 2 + j] = W0[(row0 + r) * 16 + kq * 2 + j];
        const float4* W1 = (const float4*)Wv1;
        #pragma unroll
        for (int r = 0; r < 4; r++)
            #pragma unroll
            for (int j = 0; j < 4; j++)
                w1r[r * 4 + j] = W1[(row0 + r) * 32 + kq * 4 + j];
        const float4* W2 = (const float4*)Wv2;
        #pragma unroll
        for (int r = 0; r < 4; r++)
            #pragma unroll
            for (int j = 0; j < 4; j++)
                w2r[r * 4 + j] = W2[(kH * rank + row0 + r) * 32 + kq * 4 + j];
    }

    // ---- staging ----
    for (int i = t; i < kH; i += NT) {
        sm[OFF_BV0 + i]  = bv0[i];
        sm[OFF_BV1 + i]  = bv1[i];
        sm[OFF_BV2S + i] = bv2[kH * rank + i];
    }
    for (int i = t; i < kOut * kS; i += NT) sm[OFF_WR + i] = Wr[i];
    if (t < kOut) sm[OFF_BR + t] = br[t];
    {
        const float* src = &g_sigs[(size_t)b * kNW * 36];
        for (int i = t; i < kNW * 36; i += NT) sm[OFF_SIGS + i] = src[i];
    }
    if (t < kS) sm[OFF_HH + t] = g_h0[b * kS + t];
    __syncthreads();

    // ---- precompute C coefficients for all steps (this rank's channels) ----
    for (int i = t; i < kNW * 16; i += NT) {
        int n = i >> 4, j = i & 15;
        int dl = j >> 3, e = j & 7;
        int d = d0g + dl;
        const float* sgn = &sm[OFF_SIGS + n * 36];
        float v = 0.f;
        if (e < d)      v =  sgn[8 + pidx(e, d)];
        else if (e > d) v = -sgn[8 + pidx(d, e)];
        sm[OFF_CH + n * 16 + dl * 8 + e] = v;
    }

    cluster.sync();

    float4* part4  = (float4*)&sm[OFF_PART];         // ch0 region
    float4* part4b = (float4*)&sm[OFF_PART + PCH1];  // ch1 region
    const int pslot = w * 32 + kq * 4 + rg;          // this thread's float4 slot
    const int rbase0 = OFF_PART + w * 128;           // reduce base (ch0)

    // ============================ scan loop ============================
    for (int n = 0; n < kNW; n++) {

        // --- A: z0 = sp(Wv0 h + bv0)   [matvec -> warpsync -> warp reduce]
        {
            const float4* h4 = (const float4*)&sm[OFF_HH + n * kS];
            float4 a = make_float4(0.f, 0.f, 0.f, 0.f);
            #pragma unroll
            for (int j = 0; j < 2; j++) {
                float4 hv = h4[kq * 2 + j];
                a.x = dot4(w0r[0 * 2 + j], hv, a.x);
                a.y = dot4(w0r[1 * 2 + j], hv, a.y);
                a.z = dot4(w0r[2 * 2 + j], hv, a.z);
                a.w = dot4(w0r[3 * 2 + j], hv, a.w);
            }
            part4[pslot] = a;
            __syncwarp();
            if (l < 16) {
                int r = 16 * w + lr;
                float s = sm[OFF_BV0 + r];
                #pragma unroll
                for (int q = 0; q < 8; q++) s += sm[rbase0 + q * 16 + lr];
                float z, d;
                sp_sg(s, z, d);
                sm[OFF_Z0 + r] = z; sm[OFF_D0 + r] = d;
            }
        }
        __syncthreads();

        // --- B: z1 = sp(Wv1 z0 + bv1)
        {
            const float4* z4 = (const float4*)&sm[OFF_Z0];
            float4 a = make_float4(0.f, 0.f, 0.f, 0.f);
            #pragma unroll
            for (int j = 0; j < 4; j++) {
                float4 zv = z4[kq * 4 + j];
                a.x = dot4(w1r[0 * 4 + j], zv, a.x);
                a.y = dot4(w1r[1 * 4 + j], zv, a.y);
                a.z = dot4(w1r[2 * 4 + j], zv, a.z);
                a.w = dot4(w1r[3 * 4 + j], zv, a.w);
            }
            part4[pslot] = a;
            __syncwarp();
            if (l < 16) {
                int r = 16 * w + lr;
                float s = sm[OFF_BV1 + r];
                #pragma unroll
                for (int q = 0; q < 8; q++) s += sm[rbase0 + q * 16 + lr];
                float z, d;
                sp_sg(s, z, d);
                sm[OFF_Z1 + r] = z; sm[OFF_D1 + r] = d;
            }
        }
        __syncthreads();

        // --- C: V slice = tanh(Wv2s z1 + bv2s); warp reduce + push, no bar
        {
            const float4* z4 = (const float4*)&sm[OFF_Z1];
            float4 a = make_float4(0.f, 0.f, 0.f, 0.f);
            #pragma unroll
            for (int j = 0; j < 4; j++) {
                float4 zv = z4[kq * 4 + j];
                a.x = dot4(w2r[0 * 4 + j], zv, a.x);
                a.y = dot4(w2r[1 * 4 + j], zv, a.y);
                a.z = dot4(w2r[2 * 4 + j], zv, a.z);
                a.w = dot4(w2r[3 * 4 + j], zv, a.w);
            }
            part4[pslot] = a;
            __syncwarp();
            if (l < 16) {
                int r = 16 * w + lr;
                float s = sm[OFF_BV2S + r];
                #pragma unroll
                for (int q = 0; q < 8; q++) s += sm[rbase0 + q * 16 + lr];
                float v = tanh_ap(s);
                int vi = OFF_V + kH * rank + r;
                sm[vi] = v;
                sm[OFF_TDS + r] = 1.f - v * v;
                peer[0][vi] = v;
                peer[1][vi] = v;
                peer[2][vi] = v;
            }
        }
        cluster.sync();   // V(n) gathered everywhere

        // --- D: tangents w_dl = sum_e C[dl,e] V_e (own 2 channels)
        if (t < kH) {
            int dl = t >> 6, a_ = t & 63;
            const float* cj = &sm[OFF_CH + n * 16 + dl * 8];
            float acc = 0.f;
            #pragma unroll
            for (int e = 0; e < kD; e++)
                acc = fmaf(cj[e], sm[OFF_V + e * kS + a_], acc);
            sm[OFF_WT + dl * kS + a_] = acc;
        }
        __syncthreads();

        // --- E: pt_c = D0 .* (Wv0 wt_c), 2 channels; full-warp reduce
        {
            const float4* wt4 = (const float4*)&sm[OFF_WT];
            float4 a0 = make_float4(0.f, 0.f, 0.f, 0.f);
            float4 a1 = make_float4(0.f, 0.f, 0.f, 0.f);
            #pragma unroll
            for (int j = 0; j < 2; j++) {
                float4 v0 = wt4[kq * 2 + j];
                float4 v1 = wt4[16 + kq * 2 + j];
                a0.x = dot4(w0r[0 * 2 + j], v0, a0.x);
                a0.y = dot4(w0r[1 * 2 + j], v0, a0.y);
                a0.z = dot4(w0r[2 * 2 + j], v0, a0.z);
                a0.w = dot4(w0r[3 * 2 + j], v0, a0.w);
                a1.x = dot4(w0r[0 * 2 + j], v1, a1.x);
                a1.y = dot4(w0r[1 * 2 + j], v1, a1.y);
                a1.z = dot4(w0r[2 * 2 + j], v1, a1.z);
                a1.w = dot4(w0r[3 * 2 + j], v1, a1.w);
            }
            part4[pslot]  = a0;
            part4b[pslot] = a1;
            __syncwarp();
            {   // all 32 lanes: lanes 0-15 ch0 rows, 16-31 ch1 rows
                int r = 16 * w + lr;
                int base = rbase0 + lch * PCH1;
                float s = 0.f;
                #pragma unroll
                for (int q = 0; q < 8; q++) s += sm[base + q * 16 + lr];
                sm[OFF_PT + lch * kH + r] = s * sm[OFF_D0 + r];
            }
        }
        __syncthreads();

        // --- F: ut_c = D1 .* (Wv1 pt_c), 2 channels
        {
            const float4* pt4 = (const float4*)&sm[OFF_PT];
            float4 a0 = make_float4(0.f, 0.f, 0.f, 0.f);
            float4 a1 = make_float4(0.f, 0.f, 0.f, 0.f);
            #pragma unroll
            for (int j = 0; j < 4; j++) {
                float4 v0 = pt4[kq * 4 + j];
                float4 v1 = pt4[32 + kq * 4 + j];
                a0.x = dot4(w1r[0 * 4 + j], v0, a0.x);
                a0.y = dot4(w1r[1 * 4 + j], v0, a0.y);
                a0.z = dot4(w1r[2 * 4 + j], v0, a0.z);
                a0.w = dot4(w1r[3 * 4 + j], v0, a0.w);
                a1.x = dot4(w1r[0 * 4 + j], v1, a1.x);
                a1.y = dot4(w1r[1 * 4 + j], v1, a1.y);
                a1.z = dot4(w1r[2 * 4 + j], v1, a1.z);
                a1.w = dot4(w1r[3 * 4 + j], v1, a1.w);
            }
            part4[pslot]  = a0;
            part4b[pslot] = a1;
            __syncwarp();
            {
                int r = 16 * w + lr;
                int base = rbase0 + lch * PCH1;
                float s = 0.f;
                #pragma unroll
                for (int q = 0; q < 8; q++) s += sm[base + q * 16 + lr];
                sm[OFF_UT + lch * kH + r] = s * sm[OFF_D1 + r];
            }
        }
        __syncthreads();

        // --- G: rd = TDS .* (Wv2s ut_{channel(row)})
        {
            int dl = w >> 2;   // rows 16w.. belong to channel dl
            const float4* u4 = (const float4*)&sm[OFF_UT + dl * kH];
            float4 a = make_float4(0.f, 0.f, 0.f, 0.f);
            #pragma unroll
            for (int j = 0; j < 4; j++) {
                float4 uv = u4[kq * 4 + j];
                a.x = dot4(w2r[0 * 4 + j], uv, a.x);
                a.y = dot4(w2r[1 * 4 + j], uv, a.y);
                a.z = dot4(w2r[2 * 4 + j], uv, a.z);
                a.w = dot4(w2r[3 * 4 + j], uv, a.w);
            }
            part4[pslot] = a;
            __syncwarp();
            if (l < 16) {
                int r = 16 * w + lr;
                float s = 0.f;
                #pragma unroll
                for (int q = 0; q < 8; q++) s += sm[rbase0 + q * 16 + lr];
                sm[OFF_RD + r] = s * sm[OFF_TDS + r];
            }
        }
        __syncthreads();

        // --- fold: correction = rd folded + a.V(own channels); push
        if (t < kS) {
            const float* sgn = &sm[OFF_SIGS + n * 36];
            float rs = sm[OFF_RD + t] + sm[OFF_RD + kS + t]
                     + sgn[d0g]     * sm[OFF_V + d0g * kS + t]
                     + sgn[d0g + 1] * sm[OFF_V + (d0g + 1) * kS + t];
            int ri = OFF_RSLOT + kS * rank + t;
            sm[ri] = rs;
            peer[0][ri] = rs;
            peer[1][ri] = rs;
            peer[2][ri] = rs;
        }
        cluster.sync();   // corrections gathered everywhere

        // --- H: h_{n+1} = h_n + sum_p c_p
        if (t < kS) {
            float acc = sm[OFF_HH + n * kS + t];
            #pragma unroll
            for (int p = 0; p < CL; p++)
                acc += sm[OFF_RSLOT + p * kS + t];
            sm[OFF_HH + (n + 1) * kS + t] = acc;
        }
        __syncthreads();
    }

    // ---- readout of the full h history (rank 0, parallel GEMM) ----
    if (rank == 0) {
        for (int idx = t; idx < (kNW + 1) * kOut; idx += NT) {
            int n = idx >> 3, oo = idx & 7;
            float acc = sm[OFF_BR + oo];
            const float* hh = &sm[OFF_HH + n * kS];
            #pragma unroll 16
            for (int a = 0; a < kS; a++)
                acc = fmaf(sm[OFF_WR + oo * kS + a], hh[a], acc);
            out[((size_t)b * (kNW + 1) + n) * kOut + oo] = acc;
        }
    }
    cluster.sync();   // no CTA exits while peers may still touch its smem
}

extern "C" void kernel_launch(void* const* d_in, const int* in_sizes, int n_in,
                              void* d_out, int out_size) {
    // metadata order: ts, x, Wi0,bi0, Wi1,bi1, Wi2,bi2, Wv0,bv0, Wv1,bv1, Wv2,bv2, Wr,br
    const float* x   = (const float*)d_in[1];
    const float* Wi0 = (const float*)d_in[2];
    const float* bi0 = (const float*)d_in[3];
    const float* Wi1 = (const float*)d_in[4];
    const float* bi1 = (const float*)d_in[5];
    const float* Wi2 = (const float*)d_in[6];
    const float* bi2 = (const float*)d_in[7];
    const float* Wv0 = (const float*)d_in[8];
    const float* bv0 = (const float*)d_in[9];
    const float* Wv1 = (const float*)d_in[10];
    const float* bv1 = (const float*)d_in[11];
    const float* Wv2 = (const float*)d_in[12];
    const float* bv2 = (const float*)d_in[13];
    const float* Wr  = (const float*)d_in[14];
    const float* br  = (const float*)d_in[15];
    float* out = (float*)d_out;

    logncde_prep_kernel<<<PREPBLK, 256>>>(x, Wi0, bi0, Wi1, bi1, Wi2, bi2);

    cudaFuncSetAttribute(logncde_v16_kernel,
                         cudaFuncAttributeMaxDynamicSharedMemorySize,
                         SMEMF * (int)sizeof(float));
    logncde_v16_kernel<<<kB * CL, NT, SMEMF * sizeof(float)>>>(
        Wv0, bv0, Wv1, bv1, Wv2, bv2, Wr, br, out);
}